// round 16
// baseline (speedup 1.0000x reference)
#include <cuda_runtime.h>
#include <cstdint>
#include <cstddef>

typedef unsigned long long ull;

#define BB 64
#define TT 1024
#define DD 256
#define UU 256
#define MM (BB*TT)

// scan: 512 threads; thread = (u_lo, kq) with lane = kq*8 + (u&7)
// covers columns u_lo and u_lo+128 over k in [kq*64, kq*64+64).
// per column: 22 weight pairs in regs, 10 streamed  -> 44 reg pairs total
#define WS_BYTES (10*512*16)   // 80 KB (10 ulonglong2 entries per thread)

// producer->consumer flags: gemm chunk (b, c) covers t in [c*32, c*32+32)
__device__ int g_flag[BB][TT/32];    // 8 KB static

// ---------------- packed f32x2 helpers ----------------
__device__ __forceinline__ ull fma2(ull a, ull b, ull c){
    ull d;
    asm("fma.rn.f32x2 %0, %1, %2, %3;" : "=l"(d) : "l"(a), "l"(b), "l"(c));
    return d;
}
__device__ __forceinline__ float2 unpack2(ull a){
    float2 r;
    asm("mov.b64 {%0, %1}, %2;" : "=f"(r.x), "=f"(r.y) : "l"(a));
    return r;
}
__device__ __forceinline__ ull pack2(float lo, float hi){
    ull p;
    asm("mov.b64 %0, {%1, %2};" : "=l"(p) : "f"(lo), "f"(hi));
    return p;
}
__device__ __forceinline__ ull wload(const float* W, int k, int u){
    return pack2(W[(size_t)k*UU + u], W[(size_t)(k+1)*UU + u]);
}
__device__ __forceinline__ float fast_tanh(float x){
    float xc = fminf(fmaxf(x, -15.f), 15.f);
    float e  = __expf(2.f*xc);
    return __fdividef(e - 1.f, e + 1.f);
}

// ---------------- flag clear (runs before the fused kernel each replay) ----
__global__ void clear_flags(){
    int* f = &g_flag[0][0];
    #pragma unroll
    for (int i = 0; i < 4; i++) f[threadIdx.x + i*512] = 0;
}

// ---------------- fused kernel: blocks 0..63 scan, 64..2111 gemm ----------
extern __shared__ ull ws[];   // scan: 80 KB weight stream; gemm: 32 KB x-tile

#define HSEG 68               // padded segment (64 h values + 4 pad floats)

__global__ void __launch_bounds__(512,1)
fused_kernel(const float* __restrict__ X,
             const float* __restrict__ Wxh,
             const float* __restrict__ Whh,
             const float* __restrict__ bh,
             float* __restrict__ out){
    __shared__ __align__(16) float hbuf[2][4*HSEG];   // [parity][kq-seg][0..67]

    const int t = threadIdx.x;

    if (blockIdx.x >= BB){
        // ================= GEMM role: 32 rows of xW = X@Wxh + b =================
        const int g  = blockIdx.x - BB;
        const int b  = g & 63;
        const int c  = g >> 6;
        const int row0 = b*TT + c*32;
        const int u  = t & 255;
        const int rh = t >> 8;

        float* xs = (float*)ws;                 // 32 KB tile
        {
            const float4* Xv = reinterpret_cast<const float4*>(X + (size_t)row0*UU);
            float4* sv = reinterpret_cast<float4*>(xs);
            #pragma unroll
            for (int i = 0; i < 4; i++) sv[t + i*512] = Xv[t + i*512];
        }
        float bias = bh[u];
        __syncthreads();

        ull acc[16];
        #pragma unroll
        for (int r = 0; r < 16; r++) acc[r] = 0ULL;

        const float* xrows = xs + rh*16*UU;

        ull wcur[8], wnxt[8];
        #pragma unroll
        for (int j = 0; j < 8; j++) wcur[j] = wload(Wxh, 2*j, u);

        #pragma unroll 1
        for (int cc = 0; cc < 16; cc += 2){
            #pragma unroll
            for (int j = 0; j < 8; j++) wnxt[j] = wload(Wxh, 2*((cc+1)*8 + j), u);
            #pragma unroll
            for (int r = 0; r < 16; r++){
                const ulonglong2* xr = reinterpret_cast<const ulonglong2*>(xrows + r*UU) + cc*4;
                #pragma unroll
                for (int j = 0; j < 4; j++){
                    ulonglong2 xx = xr[j];
                    acc[r] = fma2(xx.x, wcur[2*j],   acc[r]);
                    acc[r] = fma2(xx.y, wcur[2*j+1], acc[r]);
                }
            }
            if (cc + 2 < 16){
                #pragma unroll
                for (int j = 0; j < 8; j++) wcur[j] = wload(Wxh, 2*((cc+2)*8 + j), u);
            }
            #pragma unroll
            for (int r = 0; r < 16; r++){
                const ulonglong2* xr = reinterpret_cast<const ulonglong2*>(xrows + r*UU) + (cc+1)*4;
                #pragma unroll
                for (int j = 0; j < 4; j++){
                    ulonglong2 xx = xr[j];
                    acc[r] = fma2(xx.x, wnxt[2*j],   acc[r]);
                    acc[r] = fma2(xx.y, wnxt[2*j+1], acc[r]);
                }
            }
        }

        #pragma unroll
        for (int r = 0; r < 16; r++){
            float2 v = unpack2(acc[r]);
            out[(size_t)(row0 + rh*16 + r)*UU + u] = v.x + v.y + bias;
        }

        __threadfence();
        __syncthreads();
        if (t == 0) *((volatile int*)&g_flag[b][c]) = 1;
        return;
    }

    // ================= SCAN role =============================================
    const int lane = t & 31;
    const int w    = t >> 5;
    const int kq   = lane >> 3;                 // 0..3 k-quarter within warp
    const int ul   = (w << 3) + (lane & 7);     // u_lo in [0,128)
    const int kb   = kq * 64;
    const int uA   = ul, uB = ul + 128;
    const int b    = blockIdx.x;

    // register-resident pairs: 22 per column (k = kb + 2j)
    ull wA[22], wB[22];
    #pragma unroll
    for (int j = 0; j < 22; j++){
        wA[j] = wload(Whh, kb + 2*j, uA);
        wB[j] = wload(Whh, kb + 2*j, uB);
    }
    // streamed: 5 ulonglong2 entries per column (k = kb+44+4i .. +3)
    ulonglong2* ws2 = reinterpret_cast<ulonglong2*>(ws);
    #pragma unroll
    for (int i = 0; i < 5; i++){
        ws2[ i     *512 + t] = make_ulonglong2(wload(Whh, kb+44+4*i, uA),
                                               wload(Whh, kb+44+4*i+2, uA));
        ws2[(5 + i)*512 + t] = make_ulonglong2(wload(Whh, kb+44+4*i, uB),
                                               wload(Whh, kb+44+4*i+2, uB));
    }

    {   // zero both parities of padded hbuf
        float* hb = &hbuf[0][0];
        for (int i = t; i < 2*4*HSEG; i += 512) hb[i] = 0.f;
    }
    __syncthreads();

    const int  uOwn  = (lane < 8) ? uA : uB;           // lanes 0..15 own a column
    const int  puOwn = ((uOwn >> 6) * HSEG) + (uOwn & 63);
    float*     rowp  = out + ((size_t)b*TT)*UU + uOwn;

    int p = 0;
    #pragma unroll 1
    for (int tt = 0; tt < TT; tt++){
        if ((tt & 31) == 0){
            if (t == 0){
                volatile int* f = &g_flag[b][tt >> 5];
                while (*f == 0) { }
                __threadfence();
            }
        }
        __syncthreads();                         // publish h(tt-1) / gate chunk

        float xw = 0.f;
        if (lane < 16) xw = rowp[0];             // pre-activation

        // hv: 16 broadcast LDS.128; kq groups hit disjoint bank quartets
        const ulonglong2* hv =
            reinterpret_cast<const ulonglong2*>(&hbuf[p][kq*HSEG]);

        ull a0 = 0ULL, a1 = 0ULL, c0 = 0ULL, c1 = 0ULL;
        #pragma unroll
        for (int i = 0; i < 11; i++){
            ulonglong2 hh = hv[i];
            a0 = fma2(hh.x, wA[2*i],   a0);
            c0 = fma2(hh.x, wB[2*i],   c0);
            a1 = fma2(hh.y, wA[2*i+1], a1);
            c1 = fma2(hh.y, wB[2*i+1], c1);
        }
        #pragma unroll
        for (int i = 0; i < 5; i++){
            ulonglong2 hh  = hv[11 + i];
            ulonglong2 wpa = ws2[ i     *512 + t];
            ulonglong2 wpb = ws2[(5 + i)*512 + t];
            a0 = fma2(hh.x, wpa.x, a0);
            c0 = fma2(hh.x, wpb.x, c0);
            a1 = fma2(hh.y, wpa.y, a1);
            c1 = fma2(hh.y, wpb.y, c1);
        }

        float2 va0 = unpack2(a0), va1 = unpack2(a1);
        float pA = (va0.x + va0.y) + (va1.x + va1.y);
        float2 vb0 = unpack2(c0), vb1 = unpack2(c1);
        float pB = (vb0.x + vb0.y) + (vb1.x + vb1.y);

        // butterfly over the 4 kq groups (lanes l, l+8, l+16, l+24)
        pA += __shfl_xor_sync(0xFFFFFFFFu, pA, 8);
        pA += __shfl_xor_sync(0xFFFFFFFFu, pA, 16);
        pB += __shfl_xor_sync(0xFFFFFFFFu, pB, 8);
        pB += __shfl_xor_sync(0xFFFFFFFFu, pB, 16);

        if (lane < 16){
            float tot = (lane < 8) ? pA : pB;
            float h = fast_tanh(tot + xw);
            hbuf[p^1][puOwn] = h;
            rowp[0] = h;
            rowp += UU;
        }
        p ^= 1;
    }
}

// ---------------- launch ----------------
extern "C" void kernel_launch(void* const* d_in, const int* in_sizes, int n_in,
                              void* d_out, int out_size){
    int idx_inputs = -1, idx_b = -1;
    int widx[2] = {-1, -1}; int nw = 0;
    for (int i = 0; i < n_in; i++){
        long long sz = in_sizes[i];
        if      (sz == (long long)MM*DD || sz == (long long)MM*DD*4) idx_inputs = i;
        else if (sz == UU || sz == UU*4)                             idx_b = i;
        else if (nw < 2)                                             widx[nw++] = i;
    }

    const float *X, *bh, *Wxh, *Whh;
    if (idx_inputs >= 0 && idx_b >= 0 && nw == 2){
        X  = (const float*)d_in[idx_inputs];
        bh = (const float*)d_in[idx_b];
        if (idx_inputs < widx[0]){
            Wxh = (const float*)d_in[widx[0]];
            Whh = (const float*)d_in[widx[1]];
        } else {
            Whh = (const float*)d_in[widx[0]];
            Wxh = (const float*)d_in[widx[1]];
        }
    } else {
        X   = (const float*)d_in[0];
        Wxh = (const float*)d_in[1];
        Whh = (const float*)d_in[2];
        bh  = (const float*)d_in[3];
    }
    float* out = (float*)d_out;                 // [64,1024,256] fp32

    cudaFuncSetAttribute(fused_kernel, cudaFuncAttributeMaxDynamicSharedMemorySize, WS_BYTES);

    clear_flags<<<1, 512>>>();
    fused_kernel<<<BB + BB*(TT/32), 512, WS_BYTES>>>(X, Wxh, Whh, bh, out);
}